// round 1
// baseline (speedup 1.0000x reference)
#include <cuda_runtime.h>
#include <math.h>

#define C_EMBD 768
#define NH     12
#define HD     64
#define T_SEQ  4096
#define BATCH  2
#define M_ROWS (BATCH * T_SEQ)   // 8192

// Scratch (no cudaMalloc allowed)
__device__ float g_qkv[(size_t)BATCH * T_SEQ * 3 * C_EMBD]; // [B,T,3C]
__device__ float g_y  [(size_t)BATCH * T_SEQ * C_EMBD];     // [B,T,C]

// ---------------------------------------------------------------------------
// SGEMM + bias: C[M,N] = A[M,K] @ B[K,N] + bias[N]
// 128x128 block tile, BK=16, 256 threads, 8x8 micro-tile. All dims divide.
// ---------------------------------------------------------------------------
__global__ __launch_bounds__(256) void sgemm_bias(
    const float* __restrict__ A, const float* __restrict__ B,
    const float* __restrict__ bias, float* __restrict__ Cm,
    int M, int N, int K)
{
    __shared__ float As[16][128];   // transposed A tile: As[k][m]
    __shared__ float Bs[16][128];   // Bs[k][n]

    const int tid = threadIdx.x;
    const int tx = tid & 15;        // 0..15 -> n
    const int ty = tid >> 4;        // 0..15 -> m

    const int by = blockIdx.y;      // M tile
    const int bx = blockIdx.x;      // N tile

    const float* Ab = A + (size_t)by * 128 * K;
    const float* Bb = B + (size_t)bx * 128;

    // A tile loads: 128x16, 2 float4 per thread
    const int a_m = tid >> 2;            // 0..63
    const int a_k = (tid & 3) * 4;       // 0,4,8,12
    // B tile loads: 16x128, 2 float4 per thread
    const int b_k = tid >> 5;            // 0..7
    const int b_n = (tid & 31) * 4;      // 0..124

    float acc[8][8];
    #pragma unroll
    for (int i = 0; i < 8; i++)
        #pragma unroll
        for (int j = 0; j < 8; j++) acc[i][j] = 0.f;

    for (int k0 = 0; k0 < K; k0 += 16) {
        float4 a0 = *(const float4*)&Ab[(size_t)a_m        * K + k0 + a_k];
        float4 a1 = *(const float4*)&Ab[(size_t)(a_m + 64) * K + k0 + a_k];
        As[a_k + 0][a_m] = a0.x; As[a_k + 1][a_m] = a0.y;
        As[a_k + 2][a_m] = a0.z; As[a_k + 3][a_m] = a0.w;
        As[a_k + 0][a_m + 64] = a1.x; As[a_k + 1][a_m + 64] = a1.y;
        As[a_k + 2][a_m + 64] = a1.z; As[a_k + 3][a_m + 64] = a1.w;

        float4 b0 = *(const float4*)&Bb[(size_t)(k0 + b_k)     * N + b_n];
        float4 b1 = *(const float4*)&Bb[(size_t)(k0 + b_k + 8) * N + b_n];
        *(float4*)&Bs[b_k    ][b_n] = b0;
        *(float4*)&Bs[b_k + 8][b_n] = b1;

        __syncthreads();

        #pragma unroll
        for (int k = 0; k < 16; k++) {
            float a[8], b[8];
            *(float4*)&a[0] = *(float4*)&As[k][ty * 8];
            *(float4*)&a[4] = *(float4*)&As[k][ty * 8 + 4];
            *(float4*)&b[0] = *(float4*)&Bs[k][tx * 8];
            *(float4*)&b[4] = *(float4*)&Bs[k][tx * 8 + 4];
            #pragma unroll
            for (int i = 0; i < 8; i++)
                #pragma unroll
                for (int j = 0; j < 8; j++)
                    acc[i][j] = fmaf(a[i], b[j], acc[i][j]);
        }
        __syncthreads();
    }

    const int cm = by * 128 + ty * 8;
    const int cn = bx * 128 + tx * 8;
    #pragma unroll
    for (int i = 0; i < 8; i++) {
        #pragma unroll
        for (int j = 0; j < 8; j += 4) {
            float4 bv = *(const float4*)&bias[cn + j];
            float4 o;
            o.x = acc[i][j + 0] + bv.x;
            o.y = acc[i][j + 1] + bv.y;
            o.z = acc[i][j + 2] + bv.z;
            o.w = acc[i][j + 3] + bv.w;
            *(float4*)&Cm[(size_t)(cm + i) * N + cn + j] = o;
        }
    }
}

// ---------------------------------------------------------------------------
// Flash attention forward, fp32. One CTA = one (b,h, 64-query block).
// Br=Bc=64, D=64, 256 threads, 4x4 micro-tiles, online softmax.
// qkv layout: [B,T,3C] with q at col h*64, k at C+h*64, v at 2C+h*64.
// Output y: [B,T,C].
// ---------------------------------------------------------------------------
#define QSTR 68
#define KSTR 65
#define VSTR 68
#define PSTR 68
#define QS(i,d) sQ[(i)*QSTR + (d)]
#define KS(j,d) sK[(j)*KSTR + (d)]
#define VS(j,d) sV[(j)*VSTR + (d)]
#define PS(i,j) sP[(i)*PSTR + (j)]

__global__ __launch_bounds__(256, 3) void flash_attn(
    const float* __restrict__ qkv, float* __restrict__ y)
{
    extern __shared__ float smem[];
    float* sQ = smem;                   // 64*68
    float* sK = sQ + 64 * QSTR;         // 64*65
    float* sV = sK + 64 * KSTR;         // 64*68
    float* sP = sV + 64 * VSTR;         // 64*68

    const int tid = threadIdx.x;
    const int tx = tid & 15;            // key / d-col group
    const int ty = tid >> 4;            // query row group
    const int qb = blockIdx.x;
    const int bh = blockIdx.y;
    const int b = bh / NH, h = bh % NH;

    const size_t rowstr = 3 * C_EMBD;
    const float* qp = qkv + ((size_t)(b * T_SEQ + qb * 64)) * rowstr + h * HD;
    const float* kp = qkv + ((size_t)b * T_SEQ) * rowstr + C_EMBD + h * HD;
    const float* vp = qkv + ((size_t)b * T_SEQ) * rowstr + 2 * C_EMBD + h * HD;

    const float scale = 0.125f; // 1/sqrt(64)

    // Load Q tile (scale folded in)
    {
        const int r0 = tid >> 4;           // 0..15
        const int d4 = (tid & 15) * 4;
        #pragma unroll
        for (int r = 0; r < 4; r++) {
            int i = r0 + r * 16;
            float4 q = *(const float4*)&qp[(size_t)i * rowstr + d4];
            QS(i, d4 + 0) = q.x * scale;
            QS(i, d4 + 1) = q.y * scale;
            QS(i, d4 + 2) = q.z * scale;
            QS(i, d4 + 3) = q.w * scale;
        }
    }

    float m_i[4], l_i[4], o[4][4];
    #pragma unroll
    for (int ii = 0; ii < 4; ii++) {
        m_i[ii] = -INFINITY;
        l_i[ii] = 0.f;
        #pragma unroll
        for (int dd = 0; dd < 4; dd++) o[ii][dd] = 0.f;
    }

    for (int t0 = 0; t0 < T_SEQ; t0 += 64) {
        // Load K, V tiles
        {
            const int r0 = tid >> 4;
            const int d4 = (tid & 15) * 4;
            #pragma unroll
            for (int r = 0; r < 4; r++) {
                int j = r0 + r * 16;
                float4 kq = *(const float4*)&kp[(size_t)(t0 + j) * rowstr + d4];
                KS(j, d4 + 0) = kq.x; KS(j, d4 + 1) = kq.y;
                KS(j, d4 + 2) = kq.z; KS(j, d4 + 3) = kq.w;
                float4 vq = *(const float4*)&vp[(size_t)(t0 + j) * rowstr + d4];
                *(float4*)&VS(j, d4) = vq;
            }
        }
        __syncthreads();

        // S = Q K^T (scaled)
        float s[4][4];
        #pragma unroll
        for (int ii = 0; ii < 4; ii++)
            #pragma unroll
            for (int jj = 0; jj < 4; jj++) s[ii][jj] = 0.f;

        #pragma unroll 8
        for (int d = 0; d < 64; d++) {
            float qv[4], kv[4];
            #pragma unroll
            for (int ii = 0; ii < 4; ii++) qv[ii] = QS(4 * ty + ii, d);
            #pragma unroll
            for (int jj = 0; jj < 4; jj++) kv[jj] = KS(4 * tx + jj, d);
            #pragma unroll
            for (int ii = 0; ii < 4; ii++)
                #pragma unroll
                for (int jj = 0; jj < 4; jj++)
                    s[ii][jj] = fmaf(qv[ii], kv[jj], s[ii][jj]);
        }

        // Online softmax per row; rows 4*ty..4*ty+3; reduce across 16 tx lanes
        #pragma unroll
        for (int ii = 0; ii < 4; ii++) {
            float rm = fmaxf(fmaxf(s[ii][0], s[ii][1]), fmaxf(s[ii][2], s[ii][3]));
            #pragma unroll
            for (int off = 1; off < 16; off <<= 1)
                rm = fmaxf(rm, __shfl_xor_sync(0xffffffffu, rm, off));
            float mnew = fmaxf(m_i[ii], rm);
            float corr = __expf(m_i[ii] - mnew);
            m_i[ii] = mnew;
            float rs = 0.f;
            #pragma unroll
            for (int jj = 0; jj < 4; jj++) {
                float p = __expf(s[ii][jj] - mnew);
                s[ii][jj] = p;
                rs += p;
            }
            #pragma unroll
            for (int off = 1; off < 16; off <<= 1)
                rs += __shfl_xor_sync(0xffffffffu, rs, off);
            l_i[ii] = l_i[ii] * corr + rs;
            #pragma unroll
            for (int dd = 0; dd < 4; dd++) o[ii][dd] *= corr;
            float4 pv = make_float4(s[ii][0], s[ii][1], s[ii][2], s[ii][3]);
            *(float4*)&PS(4 * ty + ii, 4 * tx) = pv;
        }
        __syncthreads();

        // O += P @ V
        #pragma unroll 8
        for (int j = 0; j < 64; j++) {
            float pv[4];
            #pragma unroll
            for (int ii = 0; ii < 4; ii++) pv[ii] = PS(4 * ty + ii, j);
            float4 vv = *(float4*)&VS(j, 4 * tx);
            #pragma unroll
            for (int ii = 0; ii < 4; ii++) {
                o[ii][0] = fmaf(pv[ii], vv.x, o[ii][0]);
                o[ii][1] = fmaf(pv[ii], vv.y, o[ii][1]);
                o[ii][2] = fmaf(pv[ii], vv.z, o[ii][2]);
                o[ii][3] = fmaf(pv[ii], vv.w, o[ii][3]);
            }
        }
        __syncthreads();
    }

    // Epilogue: normalize and write y[b, t, h*64 + d]
    #pragma unroll
    for (int ii = 0; ii < 4; ii++) {
        float inv = 1.f / l_i[ii];
        int t = qb * 64 + 4 * ty + ii;
        float4 ov;
        ov.x = o[ii][0] * inv;
        ov.y = o[ii][1] * inv;
        ov.z = o[ii][2] * inv;
        ov.w = o[ii][3] * inv;
        *(float4*)&y[((size_t)(b * T_SEQ + t)) * C_EMBD + h * HD + 4 * tx] = ov;
    }
}

// ---------------------------------------------------------------------------
extern "C" void kernel_launch(void* const* d_in, const int* in_sizes, int n_in,
                              void* d_out, int out_size)
{
    const float* x      = (const float*)d_in[0];
    const float* W_attn = (const float*)d_in[1];
    const float* b_attn = (const float*)d_in[2];
    const float* W_proj = (const float*)d_in[3];
    const float* b_proj = (const float*)d_in[4];
    float* out = (float*)d_out;

    float *qkv, *y;
    cudaGetSymbolAddress((void**)&qkv, g_qkv);
    cudaGetSymbolAddress((void**)&y,   g_y);

    // QKV projection: [8192,768] @ [768,2304] + bias
    dim3 g1(3 * C_EMBD / 128, M_ROWS / 128);
    sgemm_bias<<<g1, 256>>>(x, W_attn, b_attn, qkv, M_ROWS, 3 * C_EMBD, C_EMBD);

    // Flash attention
    const int smem = (64 * QSTR + 64 * KSTR + 64 * VSTR + 64 * PSTR) * (int)sizeof(float);
    cudaFuncSetAttribute(flash_attn, cudaFuncAttributeMaxDynamicSharedMemorySize, smem);
    flash_attn<<<dim3(T_SEQ / 64, BATCH * NH), 256, smem>>>(qkv, y);

    // Output projection: [8192,768] @ [768,768] + bias
    dim3 g2(C_EMBD / 128, M_ROWS / 128);
    sgemm_bias<<<g2, 256>>>(y, W_proj, b_proj, out, M_ROWS, C_EMBD, C_EMBD);
}

// round 2
// speedup vs baseline: 2.8343x; 2.8343x over previous
#include <cuda_runtime.h>
#include <math.h>

#define C_EMBD 768
#define NH     12
#define HD     64
#define T_SEQ  4096
#define BATCH  2
#define M_ROWS (BATCH * T_SEQ)   // 8192

// Scratch (no cudaMalloc allowed)
__device__ float g_qkv[(size_t)BATCH * T_SEQ * 3 * C_EMBD]; // [B,T,3C]
__device__ float g_y  [(size_t)BATCH * T_SEQ * C_EMBD];     // [B,T,C]

// fp32 -> tf32 (round to nearest) kept in a 32-bit register
__device__ __forceinline__ unsigned f2tf32(float x) {
    unsigned r;
    asm("cvt.rna.tf32.f32 %0, %1;" : "=r"(r) : "f"(x));
    return r;
}

// D += A(16x8) * B(8x8), tf32 inputs, f32 accumulate
__device__ __forceinline__ void mma16n8k8(float* c, const unsigned* a, const unsigned* b) {
    asm volatile(
        "mma.sync.aligned.m16n8k8.row.col.f32.tf32.tf32.f32 "
        "{%0,%1,%2,%3}, {%4,%5,%6,%7}, {%8,%9}, {%0,%1,%2,%3};\n"
        : "+f"(c[0]), "+f"(c[1]), "+f"(c[2]), "+f"(c[3])
        : "r"(a[0]), "r"(a[1]), "r"(a[2]), "r"(a[3]), "r"(b[0]), "r"(b[1]));
}

// ---------------------------------------------------------------------------
// TF32 GEMM + bias: C[M,N] = A[M,K] @ B[K,N] + bias[N]
// 128x128 tile, BK=32, 256 threads = 8 warps (4 along M x 2 along N).
// Warp tile 32x64 = 2 m-tiles x 8 n-tiles of m16n8k8.
// ---------------------------------------------------------------------------
#define ASTR 36   // As[m][k] row stride (32+4): frag loads conflict-free
#define BSTR 136  // Bs[k][n] row stride (128+8): frag loads conflict-free

__global__ __launch_bounds__(256) void sgemm_tf32(
    const float* __restrict__ A, const float* __restrict__ B,
    const float* __restrict__ bias, float* __restrict__ Cm,
    int M, int N, int K)
{
    __shared__ unsigned As[128 * ASTR]; // [m][k]
    __shared__ unsigned Bs[32 * BSTR];  // [k][n]

    const int tid  = threadIdx.x;
    const int warp = tid >> 5, lane = tid & 31;
    const int wm = warp & 3, wn = warp >> 2;  // 4 x 2 warp grid
    const int g = lane >> 2, c = lane & 3;    // group / thread-in-group

    const int by = blockIdx.y, bx = blockIdx.x;
    const float* Ab = A + (size_t)by * 128 * K;
    const float* Bb = B + (size_t)bx * 128;

    float acc[2][8][4];
    #pragma unroll
    for (int mt = 0; mt < 2; mt++)
        #pragma unroll
        for (int nt = 0; nt < 8; nt++)
            #pragma unroll
            for (int r = 0; r < 4; r++) acc[mt][nt][r] = 0.f;

    for (int k0 = 0; k0 < K; k0 += 32) {
        // gmem loads: 4 float4 each for A and B per thread
        float4 av[4], bv[4];
        #pragma unroll
        for (int i = 0; i < 4; i++) {
            int idx = tid + i * 256;
            av[i] = *(const float4*)&Ab[(size_t)(idx >> 3) * K + k0 + (idx & 7) * 4];
            bv[i] = *(const float4*)&Bb[(size_t)(k0 + (idx >> 5)) * N + (idx & 31) * 4];
        }
        __syncthreads();  // previous iter's compute done reading smem
        #pragma unroll
        for (int i = 0; i < 4; i++) {
            int idx = tid + i * 256;
            int am = idx >> 3, ak = (idx & 7) * 4;
            uint4 at = make_uint4(f2tf32(av[i].x), f2tf32(av[i].y),
                                  f2tf32(av[i].z), f2tf32(av[i].w));
            *(uint4*)&As[am * ASTR + ak] = at;
            int bk = idx >> 5, bn = (idx & 31) * 4;
            uint4 bt = make_uint4(f2tf32(bv[i].x), f2tf32(bv[i].y),
                                  f2tf32(bv[i].z), f2tf32(bv[i].w));
            *(uint4*)&Bs[bk * BSTR + bn] = bt;
        }
        __syncthreads();

        #pragma unroll
        for (int ks = 0; ks < 4; ks++) {
            const int kk = ks * 8;
            unsigned a[2][4], b[8][2];
            #pragma unroll
            for (int mt = 0; mt < 2; mt++) {
                int m0 = wm * 32 + mt * 16;
                a[mt][0] = As[(m0 + g    ) * ASTR + kk + c];
                a[mt][1] = As[(m0 + g + 8) * ASTR + kk + c];
                a[mt][2] = As[(m0 + g    ) * ASTR + kk + c + 4];
                a[mt][3] = As[(m0 + g + 8) * ASTR + kk + c + 4];
            }
            #pragma unroll
            for (int nt = 0; nt < 8; nt++) {
                int n0 = wn * 64 + nt * 8;
                b[nt][0] = Bs[(kk + c    ) * BSTR + n0 + g];
                b[nt][1] = Bs[(kk + c + 4) * BSTR + n0 + g];
            }
            #pragma unroll
            for (int mt = 0; mt < 2; mt++)
                #pragma unroll
                for (int nt = 0; nt < 8; nt++)
                    mma16n8k8(acc[mt][nt], a[mt], b[nt]);
        }
    }

    // epilogue: bias + store (float2 per row-pair of each tile)
    #pragma unroll
    for (int mt = 0; mt < 2; mt++) {
        #pragma unroll
        for (int nt = 0; nt < 8; nt++) {
            int row0 = by * 128 + wm * 32 + mt * 16 + g;
            int col  = bx * 128 + wn * 64 + nt * 8 + 2 * c;
            float2 bv = *(const float2*)&bias[col];
            float2 o0 = make_float2(acc[mt][nt][0] + bv.x, acc[mt][nt][1] + bv.y);
            float2 o1 = make_float2(acc[mt][nt][2] + bv.x, acc[mt][nt][3] + bv.y);
            *(float2*)&Cm[(size_t)row0 * N + col]       = o0;
            *(float2*)&Cm[(size_t)(row0 + 8) * N + col] = o1;
        }
    }
}

// ---------------------------------------------------------------------------
// Flash attention fwd, TF32 tensor cores. CTA = (b,h, 64-query block).
// 128 threads = 4 warps; warp owns 16 query rows. Br=Bc=64, D=64.
// Q frags live in registers; K,V,P staged in smem (tf32-converted).
// ---------------------------------------------------------------------------
#define FSTR 68   // row stride for sK/sV/sP (64+4)

__global__ __launch_bounds__(128) void flash_attn_tf32(
    const float* __restrict__ qkv, float* __restrict__ y)
{
    extern __shared__ unsigned sm[];
    unsigned* sK = sm;                 // [key][d]   64x68
    unsigned* sV = sK + 64 * FSTR;     // [key][d]   64x68
    unsigned* sP = sV + 64 * FSTR;     // [row][col] 64x68 (also Q staging)

    const int tid  = threadIdx.x;
    const int warp = tid >> 5, lane = tid & 31;
    const int g = lane >> 2, c = lane & 3;
    const int qb = blockIdx.x;
    const int bh = blockIdx.y;
    const int b = bh / NH, h = bh % NH;

    const size_t rowstr = 3 * C_EMBD;
    const float* qp = qkv + ((size_t)(b * T_SEQ + qb * 64)) * rowstr + h * HD;
    const float* kp = qkv + ((size_t)b * T_SEQ) * rowstr + C_EMBD + h * HD;
    const float* vp = qkv + ((size_t)b * T_SEQ) * rowstr + 2 * C_EMBD + h * HD;
    const float scale = 0.125f;

    // ---- stage Q (scaled) through sP, pull A-fragments into registers ----
    #pragma unroll
    for (int i = 0; i < 8; i++) {
        int idx = tid + i * 128;
        int row = idx >> 4, d4 = (idx & 15) << 2;
        float4 q = *(const float4*)&qp[(size_t)row * rowstr + d4];
        uint4 qt = make_uint4(f2tf32(q.x * scale), f2tf32(q.y * scale),
                              f2tf32(q.z * scale), f2tf32(q.w * scale));
        *(uint4*)&sP[row * FSTR + d4] = qt;
    }
    __syncthreads();
    unsigned qa[8][4];
    {
        const int r0 = 16 * warp + g;
        #pragma unroll
        for (int ks = 0; ks < 8; ks++) {
            int kk = ks * 8;
            qa[ks][0] = sP[(r0    ) * FSTR + kk + c];
            qa[ks][1] = sP[(r0 + 8) * FSTR + kk + c];
            qa[ks][2] = sP[(r0    ) * FSTR + kk + c + 4];
            qa[ks][3] = sP[(r0 + 8) * FSTR + kk + c + 4];
        }
    }
    __syncthreads();

    float m0r = -INFINITY, m1r = -INFINITY, l0 = 0.f, l1 = 0.f;
    float oc[8][4];
    #pragma unroll
    for (int dt = 0; dt < 8; dt++)
        #pragma unroll
        for (int r = 0; r < 4; r++) oc[dt][r] = 0.f;

    for (int t0 = 0; t0 < T_SEQ; t0 += 64) {
        // ---- load K,V tiles (tf32-converted) ----
        #pragma unroll
        for (int i = 0; i < 8; i++) {
            int idx = tid + i * 128;
            int row = idx >> 4, d4 = (idx & 15) << 2;
            float4 kq = *(const float4*)&kp[(size_t)(t0 + row) * rowstr + d4];
            *(uint4*)&sK[row * FSTR + d4] =
                make_uint4(f2tf32(kq.x), f2tf32(kq.y), f2tf32(kq.z), f2tf32(kq.w));
            float4 vq = *(const float4*)&vp[(size_t)(t0 + row) * rowstr + d4];
            *(uint4*)&sV[row * FSTR + d4] =
                make_uint4(f2tf32(vq.x), f2tf32(vq.y), f2tf32(vq.z), f2tf32(vq.w));
        }
        __syncthreads();

        // ---- S = Q @ K^T : 8 ksteps x 8 ntiles ----
        float sc[8][4];
        #pragma unroll
        for (int nt = 0; nt < 8; nt++)
            #pragma unroll
            for (int r = 0; r < 4; r++) sc[nt][r] = 0.f;

        #pragma unroll
        for (int ks = 0; ks < 8; ks++) {
            const int kk = ks * 8;
            #pragma unroll
            for (int nt = 0; nt < 8; nt++) {
                unsigned bfr[2];
                bfr[0] = sK[(nt * 8 + g) * FSTR + kk + c];
                bfr[1] = sK[(nt * 8 + g) * FSTR + kk + c + 4];
                mma16n8k8(sc[nt], qa[ks], bfr);
            }
        }

        // ---- online softmax (rows r0 = 16w+g, r1 = r0+8) ----
        float rm0 = -INFINITY, rm1 = -INFINITY;
        #pragma unroll
        for (int nt = 0; nt < 8; nt++) {
            rm0 = fmaxf(rm0, fmaxf(sc[nt][0], sc[nt][1]));
            rm1 = fmaxf(rm1, fmaxf(sc[nt][2], sc[nt][3]));
        }
        rm0 = fmaxf(rm0, __shfl_xor_sync(0xffffffffu, rm0, 1));
        rm0 = fmaxf(rm0, __shfl_xor_sync(0xffffffffu, rm0, 2));
        rm1 = fmaxf(rm1, __shfl_xor_sync(0xffffffffu, rm1, 1));
        rm1 = fmaxf(rm1, __shfl_xor_sync(0xffffffffu, rm1, 2));

        float mn0 = fmaxf(m0r, rm0), mn1 = fmaxf(m1r, rm1);
        float corr0 = __expf(m0r - mn0), corr1 = __expf(m1r - mn1);
        m0r = mn0; m1r = mn1;

        float s0 = 0.f, s1 = 0.f;
        #pragma unroll
        for (int nt = 0; nt < 8; nt++) {
            float p0 = __expf(sc[nt][0] - mn0); sc[nt][0] = p0; s0 += p0;
            float p1 = __expf(sc[nt][1] - mn0); sc[nt][1] = p1; s0 += p1;
            float p2 = __expf(sc[nt][2] - mn1); sc[nt][2] = p2; s1 += p2;
            float p3 = __expf(sc[nt][3] - mn1); sc[nt][3] = p3; s1 += p3;
        }
        s0 += __shfl_xor_sync(0xffffffffu, s0, 1);
        s0 += __shfl_xor_sync(0xffffffffu, s0, 2);
        s1 += __shfl_xor_sync(0xffffffffu, s1, 1);
        s1 += __shfl_xor_sync(0xffffffffu, s1, 2);
        l0 = l0 * corr0 + s0;
        l1 = l1 * corr1 + s1;

        #pragma unroll
        for (int dt = 0; dt < 8; dt++) {
            oc[dt][0] *= corr0; oc[dt][1] *= corr0;
            oc[dt][2] *= corr1; oc[dt][3] *= corr1;
        }

        // ---- write P (tf32) to sP ----
        {
            const int r0 = 16 * warp + g;
            #pragma unroll
            for (int nt = 0; nt < 8; nt++) {
                int col = nt * 8 + 2 * c;
                *(uint2*)&sP[(r0    ) * FSTR + col] =
                    make_uint2(f2tf32(sc[nt][0]), f2tf32(sc[nt][1]));
                *(uint2*)&sP[(r0 + 8) * FSTR + col] =
                    make_uint2(f2tf32(sc[nt][2]), f2tf32(sc[nt][3]));
            }
        }
        __syncthreads();

        // ---- O += P @ V : 8 ksteps (keys) x 8 dtiles ----
        {
            const int r0 = 16 * warp + g;
            #pragma unroll
            for (int ks = 0; ks < 8; ks++) {
                const int kk = ks * 8;
                unsigned pa[4];
                pa[0] = sP[(r0    ) * FSTR + kk + c];
                pa[1] = sP[(r0 + 8) * FSTR + kk + c];
                pa[2] = sP[(r0    ) * FSTR + kk + c + 4];
                pa[3] = sP[(r0 + 8) * FSTR + kk + c + 4];
                #pragma unroll
                for (int dt = 0; dt < 8; dt++) {
                    unsigned vb[2];
                    vb[0] = sV[(kk + c    ) * FSTR + dt * 8 + g];
                    vb[1] = sV[(kk + c + 4) * FSTR + dt * 8 + g];
                    mma16n8k8(oc[dt], pa, vb);
                }
            }
        }
        __syncthreads();
    }

    // ---- epilogue: normalize, write y ----
    const float inv0 = 1.f / l0, inv1 = 1.f / l1;
    const int t_0 = qb * 64 + 16 * warp + g;
    #pragma unroll
    for (int dt = 0; dt < 8; dt++) {
        int col = h * HD + dt * 8 + 2 * c;
        float2 o0 = make_float2(oc[dt][0] * inv0, oc[dt][1] * inv0);
        float2 o1 = make_float2(oc[dt][2] * inv1, oc[dt][3] * inv1);
        *(float2*)&y[((size_t)(b * T_SEQ + t_0)) * C_EMBD + col]     = o0;
        *(float2*)&y[((size_t)(b * T_SEQ + t_0 + 8)) * C_EMBD + col] = o1;
    }
}

// ---------------------------------------------------------------------------
extern "C" void kernel_launch(void* const* d_in, const int* in_sizes, int n_in,
                              void* d_out, int out_size)
{
    const float* x      = (const float*)d_in[0];
    const float* W_attn = (const float*)d_in[1];
    const float* b_attn = (const float*)d_in[2];
    const float* W_proj = (const float*)d_in[3];
    const float* b_proj = (const float*)d_in[4];
    float* out = (float*)d_out;

    float *qkv, *y;
    cudaGetSymbolAddress((void**)&qkv, g_qkv);
    cudaGetSymbolAddress((void**)&y,   g_y);

    // QKV projection: [8192,768] @ [768,2304] + bias
    dim3 g1(3 * C_EMBD / 128, M_ROWS / 128);
    sgemm_tf32<<<g1, 256>>>(x, W_attn, b_attn, qkv, M_ROWS, 3 * C_EMBD, C_EMBD);

    // Flash attention (tf32 tensor cores)
    const int smem = 3 * 64 * FSTR * (int)sizeof(unsigned);
    cudaFuncSetAttribute(flash_attn_tf32, cudaFuncAttributeMaxDynamicSharedMemorySize, smem);
    flash_attn_tf32<<<dim3(T_SEQ / 64, BATCH * NH), 128, smem>>>(qkv, y);

    // Output projection: [8192,768] @ [768,768] + bias
    dim3 g2(C_EMBD / 128, M_ROWS / 128);
    sgemm_tf32<<<g2, 256>>>(y, W_proj, b_proj, out, M_ROWS, C_EMBD, C_EMBD);
}

// round 3
// speedup vs baseline: 3.1448x; 1.1095x over previous
#include <cuda_runtime.h>
#include <math.h>

#define C_EMBD 768
#define NH     12
#define HD     64
#define T_SEQ  4096
#define BATCH  2
#define M_ROWS (BATCH * T_SEQ)   // 8192

__device__ float g_qkv[(size_t)BATCH * T_SEQ * 3 * C_EMBD]; // [B,T,3C]
__device__ float g_y  [(size_t)BATCH * T_SEQ * C_EMBD];     // [B,T,C]

__device__ __forceinline__ unsigned f2tf32(float x) {
    unsigned r;
    asm("cvt.rna.tf32.f32 %0, %1;" : "=r"(r) : "f"(x));
    return r;
}
__device__ __forceinline__ float ex2(float x) {
    float r;
    asm("ex2.approx.f32 %0, %1;" : "=f"(r) : "f"(x));
    return r;
}
__device__ __forceinline__ void mma16n8k8(float* c, const unsigned* a, const unsigned* b) {
    asm volatile(
        "mma.sync.aligned.m16n8k8.row.col.f32.tf32.tf32.f32 "
        "{%0,%1,%2,%3}, {%4,%5,%6,%7}, {%8,%9}, {%0,%1,%2,%3};\n"
        : "+f"(c[0]), "+f"(c[1]), "+f"(c[2]), "+f"(c[3])
        : "r"(a[0]), "r"(a[1]), "r"(a[2]), "r"(a[3]), "r"(b[0]), "r"(b[1]));
}
__device__ __forceinline__ unsigned smem_u32(const void* p) {
    return (unsigned)__cvta_generic_to_shared(p);
}
__device__ __forceinline__ void cp_async16(unsigned saddr, const void* g) {
    asm volatile("cp.async.cg.shared.global [%0], [%1], 16;\n" :: "r"(saddr), "l"(g));
}
#define CP_COMMIT() asm volatile("cp.async.commit_group;\n")
#define CP_WAIT(n)  asm volatile("cp.async.wait_group %0;\n" :: "n"(n))

// ---------------------------------------------------------------------------
// TF32 GEMM + bias, cp.async 2-stage pipeline. Raw fp32 in smem; cvt.rna at
// fragment load (numerics identical to cvt-at-store).
// 128x128 tile, BK=32, 256 threads = 8 warps (4 M x 2 N), warp 32x64.
// ---------------------------------------------------------------------------
#define ASTR 36
#define BSTR 136
#define GEMM_SMEM ((2 * 128 * ASTR + 2 * 32 * BSTR) * 4)

__global__ __launch_bounds__(256, 2) void sgemm_tf32(
    const float* __restrict__ A, const float* __restrict__ B,
    const float* __restrict__ bias, float* __restrict__ Cm,
    int M, int N, int K)
{
    extern __shared__ float sm[];
    float* As = sm;                    // 2 x 128 x ASTR
    float* Bs = sm + 2 * 128 * ASTR;   // 2 x 32 x BSTR

    const int tid  = threadIdx.x;
    const int warp = tid >> 5, lane = tid & 31;
    const int wm = warp & 3, wn = warp >> 2;
    const int g = lane >> 2, c = lane & 3;

    const int by = blockIdx.y, bx = blockIdx.x;
    const float* Ab = A + (size_t)by * 128 * K;
    const float* Bb = B + (size_t)bx * 128;

    float acc[2][8][4];
    #pragma unroll
    for (int mt = 0; mt < 2; mt++)
        #pragma unroll
        for (int nt = 0; nt < 8; nt++)
            #pragma unroll
            for (int r = 0; r < 4; r++) acc[mt][nt][r] = 0.f;

    // stage loader: 4 x 16B for A, 4 x 16B for B per thread
    const int am = tid >> 3,  ak = (tid & 7) * 4;    // +32 rows per chunk
    const int bk = tid >> 5,  bn = (tid & 31) * 4;   // +8 k-rows per chunk

    #define LOAD_STAGE(s, k0)                                                      \
        {                                                                          \
            _Pragma("unroll")                                                      \
            for (int i = 0; i < 4; i++) {                                          \
                cp_async16(smem_u32(&As[(s) * 128 * ASTR + (am + i * 32) * ASTR + ak]), \
                           &Ab[(size_t)(am + i * 32) * K + (k0) + ak]);            \
                cp_async16(smem_u32(&Bs[(s) * 32 * BSTR + (bk + i * 8) * BSTR + bn]),   \
                           &Bb[(size_t)((k0) + bk + i * 8) * N + bn]);             \
            }                                                                      \
        }

    LOAD_STAGE(0, 0);
    CP_COMMIT();

    const int NK = K / 32;
    for (int kt = 0; kt < NK; kt++) {
        if (kt + 1 < NK) LOAD_STAGE((kt + 1) & 1, (kt + 1) * 32);
        CP_COMMIT();
        CP_WAIT(1);
        __syncthreads();

        const float* Asb = &As[(kt & 1) * 128 * ASTR];
        const float* Bsb = &Bs[(kt & 1) * 32 * BSTR];

        #pragma unroll
        for (int ks = 0; ks < 4; ks++) {
            const int kk = ks * 8;
            unsigned a[2][4], b[8][2];
            #pragma unroll
            for (int mt = 0; mt < 2; mt++) {
                int m0 = wm * 32 + mt * 16;
                a[mt][0] = f2tf32(Asb[(m0 + g    ) * ASTR + kk + c]);
                a[mt][1] = f2tf32(Asb[(m0 + g + 8) * ASTR + kk + c]);
                a[mt][2] = f2tf32(Asb[(m0 + g    ) * ASTR + kk + c + 4]);
                a[mt][3] = f2tf32(Asb[(m0 + g + 8) * ASTR + kk + c + 4]);
            }
            #pragma unroll
            for (int nt = 0; nt < 8; nt++) {
                int n0 = wn * 64 + nt * 8;
                b[nt][0] = f2tf32(Bsb[(kk + c    ) * BSTR + n0 + g]);
                b[nt][1] = f2tf32(Bsb[(kk + c + 4) * BSTR + n0 + g]);
            }
            #pragma unroll
            for (int mt = 0; mt < 2; mt++)
                #pragma unroll
                for (int nt = 0; nt < 8; nt++)
                    mma16n8k8(acc[mt][nt], a[mt], b[nt]);
        }
        __syncthreads();
    }

    #pragma unroll
    for (int mt = 0; mt < 2; mt++) {
        #pragma unroll
        for (int nt = 0; nt < 8; nt++) {
            int row0 = by * 128 + wm * 32 + mt * 16 + g;
            int col  = bx * 128 + wn * 64 + nt * 8 + 2 * c;
            float2 bv = *(const float2*)&bias[col];
            float2 o0 = make_float2(acc[mt][nt][0] + bv.x, acc[mt][nt][1] + bv.y);
            float2 o1 = make_float2(acc[mt][nt][2] + bv.x, acc[mt][nt][3] + bv.y);
            *(float2*)&Cm[(size_t)row0 * N + col]       = o0;
            *(float2*)&Cm[(size_t)(row0 + 8) * N + col] = o1;
        }
    }
}

// ---------------------------------------------------------------------------
// Flash attention, TF32. Br=128, Bc=64, 256 threads = 8 warps (16 rows each).
// K double-buffered via cp.async; V prefetched per-tile, awaited post-softmax.
// P is warp-private (syncwarp only). ex2 with log2e folded into Q scale.
// ---------------------------------------------------------------------------
#define KS_STR 68
#define VS_STR 72
#define PQ_STR 68
#define FA_SMEM ((2 * 64 * KS_STR + 64 * VS_STR + 128 * PQ_STR) * 4)

__global__ __launch_bounds__(256, 2) void flash_attn_tf32(
    const float* __restrict__ qkv, float* __restrict__ y)
{
    extern __shared__ float sm[];
    float* sK  = sm;                      // 2 stages x [64][KS_STR]
    float* sV  = sK + 2 * 64 * KS_STR;    // [64][VS_STR]
    float* sPQ = sV + 64 * VS_STR;        // [128][PQ_STR] (Q staging, then P)

    const int tid  = threadIdx.x;
    const int warp = tid >> 5, lane = tid & 31;
    const int g = lane >> 2, c = lane & 3;
    const int qb = blockIdx.x;
    const int bh = blockIdx.y;
    const int b = bh / NH, h = bh % NH;

    const size_t rowstr = 3 * C_EMBD;
    const float* qp = qkv + ((size_t)(b * T_SEQ + qb * 128)) * rowstr + h * HD;
    const float* kp = qkv + ((size_t)b * T_SEQ) * rowstr + C_EMBD + h * HD;
    const float* vp = qkv + ((size_t)b * T_SEQ) * rowstr + 2 * C_EMBD + h * HD;
    const float qscale = 0.125f * 1.4426950408889634f; // 1/sqrt(64) * log2(e)

    // ---- stage Q (raw fp32) ----
    #pragma unroll
    for (int i = 0; i < 8; i++) {
        int idx = tid + i * 256;
        int row = idx >> 4, d4 = (idx & 15) << 2;
        *(float4*)&sPQ[row * PQ_STR + d4] = *(const float4*)&qp[(size_t)row * rowstr + d4];
    }
    __syncthreads();
    const int r0 = 16 * warp + g;
    unsigned qa[8][4];
    #pragma unroll
    for (int ks = 0; ks < 8; ks++) {
        int kk = ks * 8;
        qa[ks][0] = f2tf32(sPQ[(r0    ) * PQ_STR + kk + c]     * qscale);
        qa[ks][1] = f2tf32(sPQ[(r0 + 8) * PQ_STR + kk + c]     * qscale);
        qa[ks][2] = f2tf32(sPQ[(r0    ) * PQ_STR + kk + c + 4] * qscale);
        qa[ks][3] = f2tf32(sPQ[(r0 + 8) * PQ_STR + kk + c + 4] * qscale);
    }
    // (no CTA barrier needed: P writes below touch only this warp's rows)

    const int lr = tid >> 4, ld4 = (tid & 15) << 2; // K/V loader coords (+16 rows/chunk)
    #define LOAD_K(s, t0)                                                          \
        {                                                                          \
            _Pragma("unroll")                                                      \
            for (int i = 0; i < 4; i++)                                            \
                cp_async16(smem_u32(&sK[(s) * 64 * KS_STR + (lr + i * 16) * KS_STR + ld4]), \
                           &kp[(size_t)((t0) + lr + i * 16) * rowstr + ld4]);      \
        }
    #define LOAD_V(t0)                                                             \
        {                                                                          \
            _Pragma("unroll")                                                      \
            for (int i = 0; i < 4; i++)                                            \
                cp_async16(smem_u32(&sV[(lr + i * 16) * VS_STR + ld4]),            \
                           &vp[(size_t)((t0) + lr + i * 16) * rowstr + ld4]);      \
        }

    LOAD_K(0, 0);
    CP_COMMIT();

    float m0r = -INFINITY, m1r = -INFINITY, l0 = 0.f, l1 = 0.f;
    float oc[8][4];
    #pragma unroll
    for (int dt = 0; dt < 8; dt++)
        #pragma unroll
        for (int r = 0; r < 4; r++) oc[dt][r] = 0.f;

    const int NT = T_SEQ / 64;
    for (int t = 0; t < NT; t++) {
        const int t0 = t * 64;
        __syncthreads();                 // all warps done with sV / K stage being overwritten
        if (t + 1 < NT) LOAD_K((t + 1) & 1, t0 + 64);
        LOAD_V(t0);
        CP_COMMIT();
        CP_WAIT(1);                      // K(t) arrived
        __syncthreads();                 // make K(t) visible CTA-wide

        const float* Kb = &sK[(t & 1) * 64 * KS_STR];

        // ---- S = Q @ K^T ----
        float sc[8][4];
        #pragma unroll
        for (int nt = 0; nt < 8; nt++)
            #pragma unroll
            for (int r = 0; r < 4; r++) sc[nt][r] = 0.f;

        #pragma unroll
        for (int ks = 0; ks < 8; ks++) {
            const int kk = ks * 8;
            unsigned bfr[8][2];
            #pragma unroll
            for (int nt = 0; nt < 8; nt++) {
                bfr[nt][0] = f2tf32(Kb[(nt * 8 + g) * KS_STR + kk + c]);
                bfr[nt][1] = f2tf32(Kb[(nt * 8 + g) * KS_STR + kk + c + 4]);
            }
            #pragma unroll
            for (int nt = 0; nt < 8; nt++)
                mma16n8k8(sc[nt], qa[ks], bfr[nt]);
        }

        // ---- online softmax (base-2 domain) ----
        float rm0 = -INFINITY, rm1 = -INFINITY;
        #pragma unroll
        for (int nt = 0; nt < 8; nt++) {
            rm0 = fmaxf(rm0, fmaxf(sc[nt][0], sc[nt][1]));
            rm1 = fmaxf(rm1, fmaxf(sc[nt][2], sc[nt][3]));
        }
        rm0 = fmaxf(rm0, __shfl_xor_sync(0xffffffffu, rm0, 1));
        rm0 = fmaxf(rm0, __shfl_xor_sync(0xffffffffu, rm0, 2));
        rm1 = fmaxf(rm1, __shfl_xor_sync(0xffffffffu, rm1, 1));
        rm1 = fmaxf(rm1, __shfl_xor_sync(0xffffffffu, rm1, 2));

        float mn0 = fmaxf(m0r, rm0), mn1 = fmaxf(m1r, rm1);
        float corr0 = ex2(m0r - mn0), corr1 = ex2(m1r - mn1);
        m0r = mn0; m1r = mn1;

        float s0 = 0.f, s1 = 0.f;
        #pragma unroll
        for (int nt = 0; nt < 8; nt++) {
            float p0 = ex2(sc[nt][0] - mn0); sc[nt][0] = p0; s0 += p0;
            float p1 = ex2(sc[nt][1] - mn0); sc[nt][1] = p1; s0 += p1;
            float p2 = ex2(sc[nt][2] - mn1); sc[nt][2] = p2; s1 += p2;
            float p3 = ex2(sc[nt][3] - mn1); sc[nt][3] = p3; s1 += p3;
        }
        s0 += __shfl_xor_sync(0xffffffffu, s0, 1);
        s0 += __shfl_xor_sync(0xffffffffu, s0, 2);
        s1 += __shfl_xor_sync(0xffffffffu, s1, 1);
        s1 += __shfl_xor_sync(0xffffffffu, s1, 2);
        l0 = l0 * corr0 + s0;
        l1 = l1 * corr1 + s1;

        #pragma unroll
        for (int dt = 0; dt < 8; dt++) {
            oc[dt][0] *= corr0; oc[dt][1] *= corr0;
            oc[dt][2] *= corr1; oc[dt][3] *= corr1;
        }

        // ---- write P (tf32 bits) — warp-private rows ----
        #pragma unroll
        for (int nt = 0; nt < 8; nt++) {
            int col = nt * 8 + 2 * c;
            *(uint2*)&sPQ[(r0    ) * PQ_STR + col] =
                make_uint2(f2tf32(sc[nt][0]), f2tf32(sc[nt][1]));
            *(uint2*)&sPQ[(r0 + 8) * PQ_STR + col] =
                make_uint2(f2tf32(sc[nt][2]), f2tf32(sc[nt][3]));
        }
        __syncwarp();

        CP_WAIT(0);                      // V(t) arrived (hidden behind QK+softmax)
        __syncthreads();                 // V visible CTA-wide

        // ---- O += P @ V ----
        #pragma unroll
        for (int ks = 0; ks < 8; ks++) {
            const int kk = ks * 8;
            unsigned pa[4];
            pa[0] = __float_as_uint(sPQ[(r0    ) * PQ_STR + kk + c]);
            pa[1] = __float_as_uint(sPQ[(r0 + 8) * PQ_STR + kk + c]);
            pa[2] = __float_as_uint(sPQ[(r0    ) * PQ_STR + kk + c + 4]);
            pa[3] = __float_as_uint(sPQ[(r0 + 8) * PQ_STR + kk + c + 4]);
            #pragma unroll
            for (int dt = 0; dt < 8; dt++) {
                unsigned vb[2];
                vb[0] = f2tf32(sV[(kk + c    ) * VS_STR + dt * 8 + g]);
                vb[1] = f2tf32(sV[(kk + c + 4) * VS_STR + dt * 8 + g]);
                mma16n8k8(oc[dt], pa, vb);
            }
        }
    }

    // ---- epilogue ----
    const float inv0 = 1.f / l0, inv1 = 1.f / l1;
    const int t_0 = qb * 128 + r0;
    #pragma unroll
    for (int dt = 0; dt < 8; dt++) {
        int col = h * HD + dt * 8 + 2 * c;
        float2 o0 = make_float2(oc[dt][0] * inv0, oc[dt][1] * inv0);
        float2 o1 = make_float2(oc[dt][2] * inv1, oc[dt][3] * inv1);
        *(float2*)&y[((size_t)(b * T_SEQ + t_0)) * C_EMBD + col]     = o0;
        *(float2*)&y[((size_t)(b * T_SEQ + t_0 + 8)) * C_EMBD + col] = o1;
    }
}

// ---------------------------------------------------------------------------
extern "C" void kernel_launch(void* const* d_in, const int* in_sizes, int n_in,
                              void* d_out, int out_size)
{
    const float* x      = (const float*)d_in[0];
    const float* W_attn = (const float*)d_in[1];
    const float* b_attn = (const float*)d_in[2];
    const float* W_proj = (const float*)d_in[3];
    const float* b_proj = (const float*)d_in[4];
    float* out = (float*)d_out;

    float *qkv, *y;
    cudaGetSymbolAddress((void**)&qkv, g_qkv);
    cudaGetSymbolAddress((void**)&y,   g_y);

    cudaFuncSetAttribute(sgemm_tf32, cudaFuncAttributeMaxDynamicSharedMemorySize, GEMM_SMEM);
    cudaFuncSetAttribute(flash_attn_tf32, cudaFuncAttributeMaxDynamicSharedMemorySize, FA_SMEM);

    dim3 g1(3 * C_EMBD / 128, M_ROWS / 128);
    sgemm_tf32<<<g1, 256, GEMM_SMEM>>>(x, W_attn, b_attn, qkv, M_ROWS, 3 * C_EMBD, C_EMBD);

    flash_attn_tf32<<<dim3(T_SEQ / 128, BATCH * NH), 256, FA_SMEM>>>(qkv, y);

    dim3 g2(C_EMBD / 128, M_ROWS / 128);
    sgemm_tf32<<<g2, 256, GEMM_SMEM>>>(y, W_proj, b_proj, out, M_ROWS, C_EMBD, C_EMBD);
}